// round 8
// baseline (speedup 1.0000x reference)
#include <cuda_runtime.h>
#include <cuda_bf16.h>
#include <math.h>

// ---------------------------------------------------------------------------
// Problem constants
// ---------------------------------------------------------------------------
#define NB      256
#define HH      512
#define KSZ     256
#define VSZ     256
#define TT      512
#define TEXTLEN 301
#define MAXLEN  300
#define VOCAB   35

#define K1      768     // ctx(256) + h1(512)   (emb part folded into table)
#define K2      768     // h1(512) + h2(256)
#define R1      2048    // 4*H   rows, packed r = h*4 + gate
#define R2      1024    // 4*KS  rows, packed r = h*4 + gate

// ---- packed fp32x2 ops (Blackwell FFMA2 path; ptxas won't emit from C++) ----
#define FMA2(d, a, b) asm("fma.rn.f32x2 %0, %1, %2, %0;" : "+l"(d) : "l"(a), "l"(b))
#define PACK2(d, f)   asm("mov.b64 %0, {%1, %1};" : "=l"(d) : "f"(f))
#define UNPK2(lo, hi, s) asm("mov.b64 {%0, %1}, %2;" : "=f"(lo), "=f"(hi) : "l"(s))

// ---------------------------------------------------------------------------
// Device scratch
// ---------------------------------------------------------------------------
__device__ float g_W1T[K1 * R1];          // [k][r] transposed, gate-interleaved
__device__ float g_W2T[K2 * R2];
__device__ float g_embB[VOCAB * R1];      // emb@W_ih1[:, :512]^T + b_ih1 + b_hh1
__device__ float g_b2p[R2];               // b_ih2 + b_hh2, packed order
__device__ float g_h1[2][NB * HH];
__device__ float g_c1[NB * HH];
__device__ float g_h2[2][NB * KSZ];
__device__ float g_c2[NB * KSZ];
__device__ float g_ctx[NB * VSZ];
__device__ int g_nv[NB];
__device__ int g_order[NB];

__device__ __forceinline__ float sigmoidf_(float x) { return 1.f / (1.f + expf(-x)); }

// ---------------------------------------------------------------------------
// Init 1: weight transposes (gate-interleaved), packed bias, states, nv.
// ---------------------------------------------------------------------------
__global__ void init_misc(const float* __restrict__ Wih1, const float* __restrict__ Whh1,
                          const float* __restrict__ Wih2, const float* __restrict__ Whh2,
                          const float* __restrict__ bih2, const float* __restrict__ bhh2,
                          const int* __restrict__ lens)
{
    int idx = blockIdx.x * blockDim.x + threadIdx.x;
    int stride = gridDim.x * blockDim.x;

    for (int i = idx; i < K1 * R1; i += stride) {
        int k = i >> 11, r = i & (R1 - 1);
        int h = r >> 2, g = r & 3, ro = g * 512 + h;
        g_W1T[i] = (k < 256) ? Wih1[ro * 768 + 512 + k]       // ctx columns
                             : Whh1[ro * 512 + (k - 256)];    // h1 columns
    }
    for (int i = idx; i < K2 * R2; i += stride) {
        int k = i >> 10, r = i & (R2 - 1);
        int h = r >> 2, g = r & 3, ro = g * 256 + h;
        g_W2T[i] = (k < 512) ? Wih2[ro * 512 + k]
                             : Whh2[ro * 256 + (k - 512)];
    }
    for (int r = idx; r < R2; r += stride) {
        int h = r >> 2, g = r & 3, ro = g * 256 + h;
        g_b2p[r] = bih2[ro] + bhh2[ro];
    }
    for (int i = idx; i < NB * HH; i += stride) {
        g_h1[0][i] = 0.f; g_h1[1][i] = 0.f; g_c1[i] = 0.f;
    }
    for (int i = idx; i < NB * KSZ; i += stride) {
        g_h2[0][i] = 0.f; g_h2[1][i] = 0.f; g_c2[i] = 0.f; g_ctx[i] = 0.f;
    }
    for (int n = idx; n < NB; n += stride) {
        int v = lens[n] >> 3;
        if (v < 1)  v = 1;
        if (v > TT) v = TT;
        g_nv[n] = v;
    }
}

// ---------------------------------------------------------------------------
// Init 2: per-vocab precomputed gate base: emb[v] @ W_ih1[:, :512]^T + biases.
// ---------------------------------------------------------------------------
__global__ void embB_kernel(const float* __restrict__ emb, const float* __restrict__ Wih1,
                            const float* __restrict__ bih1, const float* __restrict__ bhh1)
{
    __shared__ float se[512];
    int v = blockIdx.x;
    int tid = threadIdx.x;
    se[tid]       = emb[v * HH + tid];
    se[tid + 256] = emb[v * HH + tid + 256];
    __syncthreads();
    int r = blockIdx.y * 256 + tid;
    int h = r >> 2, g = r & 3, ro = g * 512 + h;
    float acc = bih1[ro] + bhh1[ro];
    const float* __restrict__ wr = Wih1 + (size_t)ro * 768;
#pragma unroll 8
    for (int k = 0; k < 512; k++) acc = fmaf(se[k], wr[k], acc);
    g_embB[v * R1 + r] = acc;
}

// ---------------------------------------------------------------------------
// Init 3: sort batch rows by nv desc (scheduling order for attn tail).
// ---------------------------------------------------------------------------
__global__ void sort_kernel()
{
    __shared__ int snv[NB];
    int tid = threadIdx.x;
    snv[tid] = g_nv[tid];
    __syncthreads();
    int my = snv[tid];
    int rank = 0;
    for (int m = 0; m < NB; m++)
        rank += (snv[m] > my) || (snv[m] == my && m < tid);
    g_order[rank] = tid;
}

// ---------------------------------------------------------------------------
// LSTM1: gates = [ctx | h1] @ W1T + embB[tok];  cell update.
// fma.rn.f32x2 packed over r-pairs. Tile 64r x 32n, 128 threads,
// thread tile 8r x 2n. Double-buffered, one sync/chunk. Grid (32,8)=256.
// ---------------------------------------------------------------------------
#define L1_NC (K1 / 32)       // 24 chunks

__global__ __launch_bounds__(128) void lstm1_kernel(const int* __restrict__ text,
                                                    int step, int par)
{
    __shared__ __align__(16) float Ws[2][32][64];
    __shared__ __align__(16) float Ad[2][32][68];   // A duplicated: cols 2n,2n+1

    const int tid = threadIdx.x;
    const int tx = tid & 7;           // rows rb + tx*8 .. +7
    const int ty = tid >> 3;          // 0..15: n = nb + ty*2, +1
    const int rb = blockIdx.x * 64;
    const int nb = blockIdx.y * 32;

    const float* __restrict__ h1p = g_h1[par];
    float* __restrict__ h1n = g_h1[par ^ 1];

    // staging maps
    const int wc4 = tid & 15;         // W float4 column
    const int wk0 = tid >> 4;         // W k rows wk0 + 8j
    const int an  = tid >> 2;         // A batch row nb+an (0..31)
    const int ak  = tid & 3;          // A k offsets ak + 4j (j 0..7)

    unsigned long long acc[4][2];
#pragma unroll
    for (int i = 0; i < 4; i++) { acc[i][0] = 0ull; acc[i][1] = 0ull; }

    float4 wreg[4];
    float  areg[8];

    // ---- prologue: chunk 0 ----
    {
#pragma unroll
        for (int j = 0; j < 4; j++)
            wreg[j] = *(const float4*)&g_W1T[(size_t)(wk0 + 8 * j) * R1 + rb + wc4 * 4];
        const float* abase = g_ctx + (size_t)(nb + an) * VSZ + ak;
#pragma unroll
        for (int j = 0; j < 8; j++) areg[j] = abase[4 * j];
#pragma unroll
        for (int j = 0; j < 4; j++)
            *(float4*)&Ws[0][wk0 + 8 * j][wc4 * 4] = wreg[j];
#pragma unroll
        for (int j = 0; j < 8; j++) {
            unsigned long long d; PACK2(d, areg[j]);
            *(unsigned long long*)&Ad[0][ak + 4 * j][2 * an] = d;
        }
    }
    __syncthreads();

#pragma unroll 1
    for (int c = 0; c < L1_NC; c++) {
        if (c + 1 < L1_NC) {
            const int k0 = (c + 1) * 32;
#pragma unroll
            for (int j = 0; j < 4; j++)
                wreg[j] = *(const float4*)&g_W1T[(size_t)(k0 + wk0 + 8 * j) * R1 + rb + wc4 * 4];
            const float* abase = (k0 < 256)
                ? g_ctx + (size_t)(nb + an) * VSZ + (k0 + ak)
                : h1p   + (size_t)(nb + an) * HH  + (k0 - 256 + ak);
#pragma unroll
            for (int j = 0; j < 8; j++) areg[j] = abase[4 * j];
        }
        const int buf = c & 1;
#pragma unroll
        for (int k = 0; k < 32; k++) {
            ulonglong2 w01 = *(const ulonglong2*)&Ws[buf][k][tx * 8];
            ulonglong2 w23 = *(const ulonglong2*)&Ws[buf][k][tx * 8 + 4];
            ulonglong2 aa  = *(const ulonglong2*)&Ad[buf][k][ty * 4];
            FMA2(acc[0][0], w01.x, aa.x); FMA2(acc[0][1], w01.x, aa.y);
            FMA2(acc[1][0], w01.y, aa.x); FMA2(acc[1][1], w01.y, aa.y);
            FMA2(acc[2][0], w23.x, aa.x); FMA2(acc[2][1], w23.x, aa.y);
            FMA2(acc[3][0], w23.y, aa.x); FMA2(acc[3][1], w23.y, aa.y);
        }
        if (c + 1 < L1_NC) {
            const int nbuf = buf ^ 1;
#pragma unroll
            for (int j = 0; j < 4; j++)
                *(float4*)&Ws[nbuf][wk0 + 8 * j][wc4 * 4] = wreg[j];
#pragma unroll
            for (int j = 0; j < 8; j++) {
                unsigned long long d; PACK2(d, areg[j]);
                *(unsigned long long*)&Ad[nbuf][ak + 4 * j][2 * an] = d;
            }
            __syncthreads();
        }
    }

    // ---- epilogue: add embB[tok], cell update (2 h-units x 2 n) ----
    const int hbase = (rb >> 2) + tx * 2;
#pragma unroll
    for (int j = 0; j < 2; j++) {
        int n = nb + ty * 2 + j;
        int tok = __ldg(&text[n * TEXTLEN + step]);
        const float* eb = &g_embB[(size_t)tok * R1 + rb + tx * 8];
        float4 e0 = *(const float4*)eb;
        float4 e1 = *(const float4*)(eb + 4);
        float gi, gf, gg, go;

        UNPK2(gi, gf, acc[0][j]); UNPK2(gg, go, acc[1][j]);
        gi += e0.x; gf += e0.y; gg += e0.z; go += e0.w;
        {
            int h = hbase;
            float cc = sigmoidf_(gf) * g_c1[n * HH + h] + sigmoidf_(gi) * tanhf(gg);
            g_c1[n * HH + h] = cc;
            h1n[n * HH + h] = sigmoidf_(go) * tanhf(cc);
        }
        UNPK2(gi, gf, acc[2][j]); UNPK2(gg, go, acc[3][j]);
        gi += e1.x; gf += e1.y; gg += e1.z; go += e1.w;
        {
            int h = hbase + 1;
            float cc = sigmoidf_(gf) * g_c1[n * HH + h] + sigmoidf_(gi) * tanhf(gg);
            g_c1[n * HH + h] = cc;
            h1n[n * HH + h] = sigmoidf_(go) * tanhf(cc);
        }
    }
}

// ---------------------------------------------------------------------------
// LSTM2: gates = [h1_new | h2] @ W2T + b2p;  cell update.
// Same fma2 structure. Tile 64r x 32n, 128 threads. Grid (16,8)=128.
// ---------------------------------------------------------------------------
#define L2_NC (K2 / 32)       // 24 chunks

__global__ __launch_bounds__(128) void lstm2_kernel(int par)
{
    __shared__ __align__(16) float Ws[2][32][64];
    __shared__ __align__(16) float Ad[2][32][68];

    const int tid = threadIdx.x;
    const int tx = tid & 7;
    const int ty = tid >> 3;
    const int rb = blockIdx.x * 64;
    const int nb = blockIdx.y * 32;

    const float* __restrict__ h1n = g_h1[par ^ 1];
    const float* __restrict__ h2p = g_h2[par];
    float* __restrict__ h2n = g_h2[par ^ 1];

    const int wc4 = tid & 15;
    const int wk0 = tid >> 4;
    const int an  = tid >> 2;
    const int ak  = tid & 3;

    unsigned long long acc[4][2];
#pragma unroll
    for (int i = 0; i < 4; i++) { acc[i][0] = 0ull; acc[i][1] = 0ull; }

    float4 wreg[4];
    float  areg[8];

    {
#pragma unroll
        for (int j = 0; j < 4; j++)
            wreg[j] = *(const float4*)&g_W2T[(size_t)(wk0 + 8 * j) * R2 + rb + wc4 * 4];
        const float* abase = h1n + (size_t)(nb + an) * HH + ak;
#pragma unroll
        for (int j = 0; j < 8; j++) areg[j] = abase[4 * j];
#pragma unroll
        for (int j = 0; j < 4; j++)
            *(float4*)&Ws[0][wk0 + 8 * j][wc4 * 4] = wreg[j];
#pragma unroll
        for (int j = 0; j < 8; j++) {
            unsigned long long d; PACK2(d, areg[j]);
            *(unsigned long long*)&Ad[0][ak + 4 * j][2 * an] = d;
        }
    }
    __syncthreads();

#pragma unroll 1
    for (int c = 0; c < L2_NC; c++) {
        if (c + 1 < L2_NC) {
            const int k0 = (c + 1) * 32;
#pragma unroll
            for (int j = 0; j < 4; j++)
                wreg[j] = *(const float4*)&g_W2T[(size_t)(k0 + wk0 + 8 * j) * R2 + rb + wc4 * 4];
            const float* abase = (k0 < 512)
                ? h1n + (size_t)(nb + an) * HH  + (k0 + ak)
                : h2p + (size_t)(nb + an) * KSZ + (k0 - 512 + ak);
#pragma unroll
            for (int j = 0; j < 8; j++) areg[j] = abase[4 * j];
        }
        const int buf = c & 1;
#pragma unroll
        for (int k = 0; k < 32; k++) {
            ulonglong2 w01 = *(const ulonglong2*)&Ws[buf][k][tx * 8];
            ulonglong2 w23 = *(const ulonglong2*)&Ws[buf][k][tx * 8 + 4];
            ulonglong2 aa  = *(const ulonglong2*)&Ad[buf][k][ty * 4];
            FMA2(acc[0][0], w01.x, aa.x); FMA2(acc[0][1], w01.x, aa.y);
            FMA2(acc[1][0], w01.y, aa.x); FMA2(acc[1][1], w01.y, aa.y);
            FMA2(acc[2][0], w23.x, aa.x); FMA2(acc[2][1], w23.x, aa.y);
            FMA2(acc[3][0], w23.y, aa.x); FMA2(acc[3][1], w23.y, aa.y);
        }
        if (c + 1 < L2_NC) {
            const int nbuf = buf ^ 1;
#pragma unroll
            for (int j = 0; j < 4; j++)
                *(float4*)&Ws[nbuf][wk0 + 8 * j][wc4 * 4] = wreg[j];
#pragma unroll
            for (int j = 0; j < 8; j++) {
                unsigned long long d; PACK2(d, areg[j]);
                *(unsigned long long*)&Ad[nbuf][ak + 4 * j][2 * an] = d;
            }
            __syncthreads();
        }
    }

    const int hbase = (rb >> 2) + tx * 2;
    const float* bb = &g_b2p[rb + tx * 8];
    float4 b0 = *(const float4*)bb;
    float4 b1 = *(const float4*)(bb + 4);
#pragma unroll
    for (int j = 0; j < 2; j++) {
        int n = nb + ty * 2 + j;
        float gi, gf, gg, go;

        UNPK2(gi, gf, acc[0][j]); UNPK2(gg, go, acc[1][j]);
        gi += b0.x; gf += b0.y; gg += b0.z; go += b0.w;
        {
            int h = hbase;
            float cc = sigmoidf_(gf) * g_c2[n * KSZ + h] + sigmoidf_(gi) * tanhf(gg);
            g_c2[n * KSZ + h] = cc;
            h2n[n * KSZ + h] = sigmoidf_(go) * tanhf(cc);
        }
        UNPK2(gi, gf, acc[2][j]); UNPK2(gg, go, acc[3][j]);
        gi += b1.x; gf += b1.y; gg += b1.z; go += b1.w;
        {
            int h = hbase + 1;
            float cc = sigmoidf_(gf) * g_c2[n * KSZ + h] + sigmoidf_(gi) * tanhf(gg);
            g_c2[n * KSZ + h] = cc;
            h2n[n * KSZ + h] = sigmoidf_(go) * tanhf(cc);
        }
    }
}

// ---------------------------------------------------------------------------
// Attention + output projection, fp32 K/V, high-MLP.  (unchanged, R5-proven)
// One block per batch row (length-sorted order), 512 threads / 16 warps.
// ---------------------------------------------------------------------------
__global__ __launch_bounds__(512) void attn_kernel(const float* __restrict__ enc_key,
                                                   const float* __restrict__ enc_values,
                                                   const float* __restrict__ W_out,
                                                   const float* __restrict__ b_out,
                                                   float* __restrict__ out,
                                                   int step, int par)
{
    __shared__ float sh_q[KSZ];
    __shared__ float sh_c[VSZ];
    __shared__ float sh_e[TT];
    __shared__ float sh_red[16];
    __shared__ float sh_inv;
    __shared__ float sh_acc[16][VSZ];

    const int tid = threadIdx.x;
    const int lane = tid & 31;
    const int warp = tid >> 5;
    const int n = g_order[blockIdx.x];
    const int nv = g_nv[n];

    if (tid < KSZ) sh_q[tid] = g_h2[par ^ 1][n * KSZ + tid];
    __syncthreads();

    float qr[8];
#pragma unroll
    for (int i = 0; i < 8; i++) qr[i] = sh_q[lane * 8 + i];

    // ---- energies ----
    const float* __restrict__ Kb = enc_key + (size_t)n * TT * KSZ;
    float lmax = -1e30f;
    for (int c = 0; c < nv; c += 64) {
        float4 ka[4], kb[4];
        bool act[4];
#pragma unroll
        for (int u = 0; u < 4; u++) {
            int t = c + warp + 16 * u;
            act[u] = (t < nv);
            if (act[u]) {
                const float* kr = Kb + (size_t)t * KSZ + lane * 8;
                ka[u] = *(const float4*)kr;
                kb[u] = *(const float4*)(kr + 4);
            }
        }
#pragma unroll
        for (int u = 0; u < 4; u++) {
            if (act[u]) {
                float s = qr[0] * ka[u].x + qr[1] * ka[u].y + qr[2] * ka[u].z + qr[3] * ka[u].w
                        + qr[4] * kb[u].x + qr[5] * kb[u].y + qr[6] * kb[u].z + qr[7] * kb[u].w;
#pragma unroll
                for (int o = 16; o; o >>= 1) s += __shfl_xor_sync(0xffffffffu, s, o);
                if (lane == 0) sh_e[c + warp + 16 * u] = s;
                lmax = fmaxf(lmax, s);
            }
        }
    }
    if (lane == 0) sh_red[warp] = lmax;
    __syncthreads();

    float emax = sh_red[0];
#pragma unroll
    for (int w = 1; w < 16; w++) emax = fmaxf(emax, sh_red[w]);

    float lsum = 0.f;
    for (int t = tid; t < nv; t += 512) {
        float e = expf(sh_e[t] - emax);
        sh_e[t] = e;
        lsum += e;
    }
#pragma unroll
    for (int o = 16; o; o >>= 1) lsum += __shfl_xor_sync(0xffffffffu, lsum, o);
    __syncthreads();
    if (lane == 0) sh_red[warp] = lsum;
    __syncthreads();
    if (tid == 0) {
        float tot = 0.f;
#pragma unroll
        for (int w = 0; w < 16; w++) tot += sh_red[w];
        sh_inv = 1.f / tot;
    }
    __syncthreads();
    const float inv = sh_inv;

    // ---- context ----
    const float* __restrict__ Vb = enc_values + (size_t)n * TT * VSZ;
    float acc[8];
#pragma unroll
    for (int i = 0; i < 8; i++) acc[i] = 0.f;
    for (int c = 0; c < nv; c += 64) {
        float4 va[4], vb[4];
        float ew[4];
        bool act[4];
#pragma unroll
        for (int u = 0; u < 4; u++) {
            int t = c + warp + 16 * u;
            act[u] = (t < nv);
            if (act[u]) {
                const float* vr = Vb + (size_t)t * VSZ + lane * 8;
                va[u] = *(const float4*)vr;
                vb[u] = *(const float4*)(vr + 4);
                ew[u] = sh_e[t];
            }
        }
#pragma unroll
        for (int u = 0; u < 4; u++) {
            if (act[u]) {
                float e = ew[u];
                acc[0] = fmaf(e, va[u].x, acc[0]); acc[1] = fmaf(e, va[u].y, acc[1]);
                acc[2] = fmaf(e, va[u].z, acc[2]); acc[3] = fmaf(e, va[u].w, acc[3]);
                acc[4] = fmaf(e, vb[u].x, acc[4]); acc[5] = fmaf(e, vb[u].y, acc[5]);
                acc[6] = fmaf(e, vb[u].z, acc[6]); acc[7] = fmaf(e, vb[u].w, acc[7]);
            }
        }
    }
#pragma unroll
    for (int i = 0; i < 8; i++) sh_acc[warp][lane * 8 + i] = acc[i];
    __syncthreads();

    if (tid < VSZ) {
        float ctx = 0.f;
#pragma unroll
        for (int w = 0; w < 16; w++) ctx += sh_acc[w][tid];
        ctx *= inv;
        sh_c[tid] = ctx;
        g_ctx[n * VSZ + tid] = ctx;
    }
    __syncthreads();

    // ---- output projection ----
    for (int v = warp; v < VOCAB; v += 16) {
        float s = 0.f;
        const float* __restrict__ wr = W_out + v * (KSZ + VSZ);
#pragma unroll
        for (int i = lane; i < KSZ + VSZ; i += 32) {
            float f = (i < KSZ) ? sh_q[i] : sh_c[i - KSZ];
            s = fmaf(f, wr[i], s);
        }
#pragma unroll
        for (int o = 16; o; o >>= 1) s += __shfl_xor_sync(0xffffffffu, s, o);
        if (lane == 0) out[((size_t)n * MAXLEN + step) * VOCAB + v] = s + b_out[v];
    }
}

// ---------------------------------------------------------------------------
// kernel_launch: init (3 kernels) + 300 x (lstm1, lstm2, attn)
// ---------------------------------------------------------------------------
extern "C" void kernel_launch(void* const* d_in, const int* in_sizes, int n_in,
                              void* d_out, int out_size)
{
    const float* enc_key    = (const float*)d_in[0];
    const float* enc_values = (const float*)d_in[1];
    const int*   text       = (const int*)  d_in[2];
    const int*   lens       = (const int*)  d_in[3];
    const float* emb        = (const float*)d_in[5];
    const float* W_ih1      = (const float*)d_in[6];
    const float* W_hh1      = (const float*)d_in[7];
    const float* b_ih1      = (const float*)d_in[8];
    const float* b_hh1      = (const float*)d_in[9];
    const float* W_ih2      = (const float*)d_in[10];
    const float* W_hh2      = (const float*)d_in[11];
    const float* b_ih2      = (const float*)d_in[12];
    const float* b_hh2      = (const float*)d_in[13];
    const float* W_out      = (const float*)d_in[14];
    const float* b_out      = (const float*)d_in[15];
    float* out = (float*)d_out;

    init_misc<<<1024, 256>>>(W_ih1, W_hh1, W_ih2, W_hh2, b_ih2, b_hh2, lens);
    embB_kernel<<<dim3(VOCAB, 8), 256>>>(emb, W_ih1, b_ih1, b_hh1);
    sort_kernel<<<1, 256>>>();

    for (int t = 0; t < MAXLEN; t++) {
        int par = t & 1;
        lstm1_kernel<<<dim3(32, 8), 128>>>(text, t, par);
        lstm2_kernel<<<dim3(16, 8), 128>>>(par);
        attn_kernel<<<NB, 512>>>(enc_key, enc_values, W_out, b_out, out, t, par);
    }
}

// round 9
// speedup vs baseline: 1.6076x; 1.6076x over previous
#include <cuda_runtime.h>
#include <cuda_bf16.h>
#include <math.h>

// ---------------------------------------------------------------------------
// Problem constants
// ---------------------------------------------------------------------------
#define NB      256
#define HH      512
#define KSZ     256
#define VSZ     256
#define TT      512
#define TEXTLEN 301
#define MAXLEN  300
#define VOCAB   35

#define K1      768     // ctx(256) + h1(512)   (emb part folded into table)
#define K2      768     // h1(512) + h2(256)
#define R1      2048    // 4*H   rows, packed r = h*4 + gate
#define R2      1024    // 4*KS  rows, packed r = h*4 + gate

// ---------------------------------------------------------------------------
// Device scratch
// ---------------------------------------------------------------------------
__device__ float g_W1T[K1 * R1];          // [k][r] transposed, gate-interleaved
__device__ float g_W2T[K2 * R2];
__device__ float g_embB[VOCAB * R1];      // emb@W_ih1[:, :512]^T + b_ih1 + b_hh1
__device__ float g_b2p[R2];               // b_ih2 + b_hh2, packed order
__device__ float g_h1[2][NB * HH];
__device__ float g_c1[NB * HH];
__device__ float g_h2[2][NB * KSZ];
__device__ float g_c2[NB * KSZ];
__device__ float g_ctx[NB * VSZ];
__device__ int g_nv[NB];
__device__ int g_order[NB];

__device__ __forceinline__ float sigmoidf_(float x) { return 1.f / (1.f + expf(-x)); }

// ---------------------------------------------------------------------------
// Init 1: weight transposes (gate-interleaved), packed bias, states, nv.
// ---------------------------------------------------------------------------
__global__ void init_misc(const float* __restrict__ Wih1, const float* __restrict__ Whh1,
                          const float* __restrict__ Wih2, const float* __restrict__ Whh2,
                          const float* __restrict__ bih2, const float* __restrict__ bhh2,
                          const int* __restrict__ lens)
{
    int idx = blockIdx.x * blockDim.x + threadIdx.x;
    int stride = gridDim.x * blockDim.x;

    for (int i = idx; i < K1 * R1; i += stride) {
        int k = i >> 11, r = i & (R1 - 1);
        int h = r >> 2, g = r & 3, ro = g * 512 + h;
        g_W1T[i] = (k < 256) ? Wih1[ro * 768 + 512 + k]       // ctx columns
                             : Whh1[ro * 512 + (k - 256)];    // h1 columns
    }
    for (int i = idx; i < K2 * R2; i += stride) {
        int k = i >> 10, r = i & (R2 - 1);
        int h = r >> 2, g = r & 3, ro = g * 256 + h;
        g_W2T[i] = (k < 512) ? Wih2[ro * 512 + k]
                             : Whh2[ro * 256 + (k - 512)];
    }
    for (int r = idx; r < R2; r += stride) {
        int h = r >> 2, g = r & 3, ro = g * 256 + h;
        g_b2p[r] = bih2[ro] + bhh2[ro];
    }
    for (int i = idx; i < NB * HH; i += stride) {
        g_h1[0][i] = 0.f; g_h1[1][i] = 0.f; g_c1[i] = 0.f;
    }
    for (int i = idx; i < NB * KSZ; i += stride) {
        g_h2[0][i] = 0.f; g_h2[1][i] = 0.f; g_c2[i] = 0.f; g_ctx[i] = 0.f;
    }
    for (int n = idx; n < NB; n += stride) {
        int v = lens[n] >> 3;
        if (v < 1)  v = 1;
        if (v > TT) v = TT;
        g_nv[n] = v;
    }
}

// ---------------------------------------------------------------------------
// Init 2: per-vocab precomputed gate base: emb[v] @ W_ih1[:, :512]^T + biases.
// ---------------------------------------------------------------------------
__global__ void embB_kernel(const float* __restrict__ emb, const float* __restrict__ Wih1,
                            const float* __restrict__ bih1, const float* __restrict__ bhh1)
{
    __shared__ float se[512];
    int v = blockIdx.x;
    int tid = threadIdx.x;
    se[tid]       = emb[v * HH + tid];
    se[tid + 256] = emb[v * HH + tid + 256];
    __syncthreads();
    int r = blockIdx.y * 256 + tid;
    int h = r >> 2, g = r & 3, ro = g * 512 + h;
    float acc = bih1[ro] + bhh1[ro];
    const float* __restrict__ wr = Wih1 + (size_t)ro * 768;
#pragma unroll 8
    for (int k = 0; k < 512; k++) acc = fmaf(se[k], wr[k], acc);
    g_embB[v * R1 + r] = acc;
}

// ---------------------------------------------------------------------------
// Init 3: sort batch rows by nv desc (scheduling order for attn tail).
// ---------------------------------------------------------------------------
__global__ void sort_kernel()
{
    __shared__ int snv[NB];
    int tid = threadIdx.x;
    snv[tid] = g_nv[tid];
    __syncthreads();
    int my = snv[tid];
    int rank = 0;
    for (int m = 0; m < NB; m++)
        rank += (snv[m] > my) || (snv[m] == my && m < tid);
    g_order[rank] = tid;
}

// ---------------------------------------------------------------------------
// LSTM1: gates = [ctx | h1] @ W1T + embB[tok];  cell update.
// Tile 64 rows x 32 batch, 128 threads, thread tile 4r x 4n (16 acc).
// Double-buffered (reg prefetch), ONE sync per 32-k chunk.
// Grid (32, 8) = 256 blocks -> 2 independent blocks per SM.
// ---------------------------------------------------------------------------
#define L1_NC   (K1 / 32)     // 24 chunks
#define AS1_STR 36

__global__ __launch_bounds__(128) void lstm1_kernel(const int* __restrict__ text,
                                                    int step, int par)
{
    __shared__ float Ws[2][32][64];
    __shared__ float As[2][32][AS1_STR];

    const int tid = threadIdx.x;
    const int tx = tid & 15;          // r-group: rows rb + tx*4 .. +3
    const int ty = tid >> 4;          // n-group: cols nb + ty*4 .. +3 (0..7)
    const int rb = blockIdx.x * 64;
    const int nb = blockIdx.y * 32;

    const float* __restrict__ h1p = g_h1[par];
    float* __restrict__ h1n = g_h1[par ^ 1];

    // staging thread mapping
    const int wc4 = tid & 15;         // W float4 column
    const int wk0 = tid >> 4;         // W k rows wk0 + 8j, j=0..3
    const int an  = tid >> 2;         // A batch row nb+an (0..31)
    const int ak  = tid & 3;          // A k offsets ak + 4j, j=0..7

    float acc[4][4];
#pragma unroll
    for (int i = 0; i < 4; i++)
#pragma unroll
        for (int j = 0; j < 4; j++) acc[i][j] = 0.f;

    float4 wreg[4];
    float  areg[8];

    // ---- prologue: load + store chunk 0 ----
    {
#pragma unroll
        for (int j = 0; j < 4; j++)
            wreg[j] = *(const float4*)&g_W1T[(size_t)(wk0 + 8 * j) * R1 + rb + wc4 * 4];
        const float* abase = g_ctx + (size_t)(nb + an) * VSZ + ak;
#pragma unroll
        for (int j = 0; j < 8; j++) areg[j] = abase[4 * j];
#pragma unroll
        for (int j = 0; j < 4; j++)
            *(float4*)&Ws[0][wk0 + 8 * j][wc4 * 4] = wreg[j];
#pragma unroll
        for (int j = 0; j < 8; j++) As[0][ak + 4 * j][an] = areg[j];
    }
    __syncthreads();

#pragma unroll 1
    for (int c = 0; c < L1_NC; c++) {
        // prefetch chunk c+1 into registers
        if (c + 1 < L1_NC) {
            const int k0 = (c + 1) * 32;
#pragma unroll
            for (int j = 0; j < 4; j++)
                wreg[j] = *(const float4*)&g_W1T[(size_t)(k0 + wk0 + 8 * j) * R1 + rb + wc4 * 4];
            const float* abase = (k0 < 256)
                ? g_ctx + (size_t)(nb + an) * VSZ + (k0 + ak)
                : h1p   + (size_t)(nb + an) * HH  + (k0 - 256 + ak);
#pragma unroll
            for (int j = 0; j < 8; j++) areg[j] = abase[4 * j];
        }
        // compute current buffer
        const int buf = c & 1;
#pragma unroll
        for (int k = 0; k < 32; k++) {
            float4 w = *(float4*)&Ws[buf][k][tx * 4];
            float4 a = *(float4*)&As[buf][k][ty * 4];
            acc[0][0] = fmaf(w.x, a.x, acc[0][0]); acc[0][1] = fmaf(w.x, a.y, acc[0][1]);
            acc[0][2] = fmaf(w.x, a.z, acc[0][2]); acc[0][3] = fmaf(w.x, a.w, acc[0][3]);
            acc[1][0] = fmaf(w.y, a.x, acc[1][0]); acc[1][1] = fmaf(w.y, a.y, acc[1][1]);
            acc[1][2] = fmaf(w.y, a.z, acc[1][2]); acc[1][3] = fmaf(w.y, a.w, acc[1][3]);
            acc[2][0] = fmaf(w.z, a.x, acc[2][0]); acc[2][1] = fmaf(w.z, a.y, acc[2][1]);
            acc[2][2] = fmaf(w.z, a.z, acc[2][2]); acc[2][3] = fmaf(w.z, a.w, acc[2][3]);
            acc[3][0] = fmaf(w.w, a.x, acc[3][0]); acc[3][1] = fmaf(w.w, a.y, acc[3][1]);
            acc[3][2] = fmaf(w.w, a.z, acc[3][2]); acc[3][3] = fmaf(w.w, a.w, acc[3][3]);
        }
        // store prefetched chunk into alternate buffer
        if (c + 1 < L1_NC) {
            const int nbuf = buf ^ 1;
#pragma unroll
            for (int j = 0; j < 4; j++)
                *(float4*)&Ws[nbuf][wk0 + 8 * j][wc4 * 4] = wreg[j];
#pragma unroll
            for (int j = 0; j < 8; j++) As[nbuf][ak + 4 * j][an] = areg[j];
            __syncthreads();
        }
    }

    // ---- epilogue: add embB[tok], cell update ----
    const int h = (rb >> 2) + tx;          // hidden index (4 gates per h)
#pragma unroll
    for (int j = 0; j < 4; j++) {
        int n = nb + ty * 4 + j;
        int tok = __ldg(&text[n * TEXTLEN + step]);
        float4 eb = *(const float4*)&g_embB[tok * R1 + rb + tx * 4];
        float gi = acc[0][j] + eb.x;
        float gf = acc[1][j] + eb.y;
        float gg = acc[2][j] + eb.z;
        float go = acc[3][j] + eb.w;
        float c = sigmoidf_(gf) * g_c1[n * HH + h] + sigmoidf_(gi) * tanhf(gg);
        g_c1[n * HH + h] = c;
        h1n[n * HH + h] = sigmoidf_(go) * tanhf(c);
    }
}

// ---------------------------------------------------------------------------
// LSTM2: gates = [h1_new | h2] @ W2T + b2p;  cell update.   (R7 version)
// Tile 64 rows x 32 batch, 256 threads, thread tile 4r x 2n.
// Double-buffered, one sync per chunk. Grid (16, 8) = 128 blocks.
// ---------------------------------------------------------------------------
#define L2_NC   (K2 / 32)     // 24 chunks
#define AS2_STR 34

__global__ __launch_bounds__(256) void lstm2_kernel(int par)
{
    __shared__ float Ws[2][32][64];
    __shared__ float As[2][32][AS2_STR];

    const int tid = threadIdx.x;
    const int tx = tid & 15;          // r-group
    const int ty = tid >> 4;          // n-pair: cols nb + ty*2, +1
    const int rb = blockIdx.x * 64;
    const int nb = blockIdx.y * 32;

    const float* __restrict__ h1n = g_h1[par ^ 1];
    const float* __restrict__ h2p = g_h2[par];
    float* __restrict__ h2n = g_h2[par ^ 1];

    const int wk = tid >> 4;
    const int wc4 = tid & 15;
    const int an = tid >> 3;          // 0..31
    const int ak = tid & 7;           // k offsets ak + 8j, j=0..3

    float acc[4][2];
#pragma unroll
    for (int i = 0; i < 4; i++) { acc[i][0] = 0.f; acc[i][1] = 0.f; }

    float4 wreg0, wreg1;
    float areg[4];

    {
        const int k0 = 0;
        wreg0 = *(const float4*)&g_W2T[(size_t)(k0 + wk) * R2 + rb + wc4 * 4];
        wreg1 = *(const float4*)&g_W2T[(size_t)(k0 + wk + 16) * R2 + rb + wc4 * 4];
        const float* abase = h1n + (size_t)(nb + an) * HH + (k0 + ak);
#pragma unroll
        for (int j = 0; j < 4; j++) areg[j] = abase[8 * j];
        *(float4*)&Ws[0][wk][wc4 * 4]      = wreg0;
        *(float4*)&Ws[0][wk + 16][wc4 * 4] = wreg1;
#pragma unroll
        for (int j = 0; j < 4; j++) As[0][ak + 8 * j][an] = areg[j];
    }
    __syncthreads();

#pragma unroll 1
    for (int c = 0; c < L2_NC; c++) {
        if (c + 1 < L2_NC) {
            const int k0 = (c + 1) * 32;
            wreg0 = *(const float4*)&g_W2T[(size_t)(k0 + wk) * R2 + rb + wc4 * 4];
            wreg1 = *(const float4*)&g_W2T[(size_t)(k0 + wk + 16) * R2 + rb + wc4 * 4];
            const float* abase = (k0 < 512)
                ? h1n + (size_t)(nb + an) * HH  + (k0 + ak)
                : h2p + (size_t)(nb + an) * KSZ + (k0 - 512 + ak);
#pragma unroll
            for (int j = 0; j < 4; j++) areg[j] = abase[8 * j];
        }
        const int buf = c & 1;
#pragma unroll
        for (int k = 0; k < 32; k++) {
            float4 w = *(float4*)&Ws[buf][k][tx * 4];
            float2 a = *(float2*)&As[buf][k][ty * 2];
            acc[0][0] = fmaf(w.x, a.x, acc[0][0]); acc[0][1] = fmaf(w.x, a.y, acc[0][1]);
            acc[1][0] = fmaf(w.y, a.x, acc[1][0]); acc[1][1] = fmaf(w.y, a.y, acc[1][1]);
            acc[2][0] = fmaf(w.z, a.x, acc[2][0]); acc[2][1] = fmaf(w.z, a.y, acc[2][1]);
            acc[3][0] = fmaf(w.w, a.x, acc[3][0]); acc[3][1] = fmaf(w.w, a.y, acc[3][1]);
        }
        if (c + 1 < L2_NC) {
            const int nbuf = buf ^ 1;
            *(float4*)&Ws[nbuf][wk][wc4 * 4]      = wreg0;
            *(float4*)&Ws[nbuf][wk + 16][wc4 * 4] = wreg1;
#pragma unroll
            for (int j = 0; j < 4; j++) As[nbuf][ak + 8 * j][an] = areg[j];
            __syncthreads();
        }
    }

    const int h = (rb >> 2) + tx;
    const int r4 = rb + tx * 4;
    const float bi = g_b2p[r4 + 0];
    const float bf = g_b2p[r4 + 1];
    const float bg = g_b2p[r4 + 2];
    const float bo = g_b2p[r4 + 3];
#pragma unroll
    for (int j = 0; j < 2; j++) {
        int n = nb + ty * 2 + j;
        float gi = acc[0][j] + bi;
        float gf = acc[1][j] + bf;
        float gg = acc[2][j] + bg;
        float go = acc[3][j] + bo;
        float c = sigmoidf_(gf) * g_c2[n * KSZ + h] + sigmoidf_(gi) * tanhf(gg);
        g_c2[n * KSZ + h] = c;
        h2n[n * KSZ + h] = sigmoidf_(go) * tanhf(c);
    }
}

// ---------------------------------------------------------------------------
// Attention + output projection, fp32 K/V, high-MLP.  (unchanged, R5-proven)
// One block per batch row (length-sorted order), 512 threads / 16 warps.
// ---------------------------------------------------------------------------
__global__ __launch_bounds__(512) void attn_kernel(const float* __restrict__ enc_key,
                                                   const float* __restrict__ enc_values,
                                                   const float* __restrict__ W_out,
                                                   const float* __restrict__ b_out,
                                                   float* __restrict__ out,
                                                   int step, int par)
{
    __shared__ float sh_q[KSZ];
    __shared__ float sh_c[VSZ];
    __shared__ float sh_e[TT];
    __shared__ float sh_red[16];
    __shared__ float sh_inv;
    __shared__ float sh_acc[16][VSZ];

    const int tid = threadIdx.x;
    const int lane = tid & 31;
    const int warp = tid >> 5;
    const int n = g_order[blockIdx.x];
    const int nv = g_nv[n];

    if (tid < KSZ) sh_q[tid] = g_h2[par ^ 1][n * KSZ + tid];
    __syncthreads();

    float qr[8];
#pragma unroll
    for (int i = 0; i < 8; i++) qr[i] = sh_q[lane * 8 + i];

    // ---- energies ----
    const float* __restrict__ Kb = enc_key + (size_t)n * TT * KSZ;
    float lmax = -1e30f;
    for (int c = 0; c < nv; c += 64) {
        float4 ka[4], kb[4];
        bool act[4];
#pragma unroll
        for (int u = 0; u < 4; u++) {
            int t = c + warp + 16 * u;
            act[u] = (t < nv);
            if (act[u]) {
                const float* kr = Kb + (size_t)t * KSZ + lane * 8;
                ka[u] = *(const float4*)kr;
                kb[u] = *(const float4*)(kr + 4);
            }
        }
#pragma unroll
        for (int u = 0; u < 4; u++) {
            if (act[u]) {
                float s = qr[0] * ka[u].x + qr[1] * ka[u].y + qr[2] * ka[u].z + qr[3] * ka[u].w
                        + qr[4] * kb[u].x + qr[5] * kb[u].y + qr[6] * kb[u].z + qr[7] * kb[u].w;
#pragma unroll
                for (int o = 16; o; o >>= 1) s += __shfl_xor_sync(0xffffffffu, s, o);
                if (lane == 0) sh_e[c + warp + 16 * u] = s;
                lmax = fmaxf(lmax, s);
            }
        }
    }
    if (lane == 0) sh_red[warp] = lmax;
    __syncthreads();

    float emax = sh_red[0];
#pragma unroll
    for (int w = 1; w < 16; w++) emax = fmaxf(emax, sh_red[w]);

    float lsum = 0.f;
    for (int t = tid; t < nv; t += 512) {
        float e = expf(sh_e[t] - emax);
        sh_e[t] = e;
        lsum += e;
    }
#pragma unroll
    for (int o = 16; o; o >>= 1) lsum += __shfl_xor_sync(0xffffffffu, lsum, o);
    __syncthreads();
    if (lane == 0) sh_red[warp] = lsum;
    __syncthreads();
    if (tid == 0) {
        float tot = 0.f;
#pragma unroll
        for (int w = 0; w < 16; w++) tot += sh_red[w];
        sh_inv = 1.f / tot;
    }
    __syncthreads();
    const float inv = sh_inv;

    // ---- context ----
    const float* __restrict__ Vb = enc_values + (size_t)n * TT * VSZ;
    float acc[8];
#pragma unroll
    for (int i = 0; i < 8; i++) acc[i] = 0.f;
    for (int c = 0; c < nv; c += 64) {
        float4 va[4], vb[4];
        float ew[4];
        bool act[4];
#pragma unroll
        for (int u = 0; u < 4; u++) {
            int t = c + warp + 16 * u;
            act[u] = (t < nv);
            if (act[u]) {
                const float* vr = Vb + (size_t)t * VSZ + lane * 8;
                va[u] = *(const float4*)vr;
                vb[u] = *(const float4*)(vr + 4);
                ew[u] = sh_e[t];
            }
        }
#pragma unroll
        for (int u = 0; u < 4; u++) {
            if (act[u]) {
                float e = ew[u];
                acc[0] = fmaf(e, va[u].x, acc[0]); acc[1] = fmaf(e, va[u].y, acc[1]);
                acc[2] = fmaf(e, va[u].z, acc[2]); acc[3] = fmaf(e, va[u].w, acc[3]);
                acc[4] = fmaf(e, vb[u].x, acc[4]); acc[5] = fmaf(e, vb[u].y, acc[5]);
                acc[6] = fmaf(e, vb[u].z, acc[6]); acc[7] = fmaf(e, vb[u].w, acc[7]);
            }
        }
    }
#pragma unroll
    for (int i = 0; i < 8; i++) sh_acc[warp][lane * 8 + i] = acc[i];
    __syncthreads();

    if (tid < VSZ) {
        float ctx = 0.f;
#pragma unroll
        for (int w = 0; w < 16; w++) ctx += sh_acc[w][tid];
        ctx *= inv;
        sh_c[tid] = ctx;
        g_ctx[n * VSZ + tid] = ctx;
    }
    __syncthreads();

    // ---- output projection ----
    for (int v = warp; v < VOCAB; v += 16) {
        float s = 0.f;
        const float* __restrict__ wr = W_out + v * (KSZ + VSZ);
#pragma unroll
        for (int i = lane; i < KSZ + VSZ; i += 32) {
            float f = (i < KSZ) ? sh_q[i] : sh_c[i - KSZ];
            s = fmaf(f, wr[i], s);
        }
#pragma unroll
        for (int o = 16; o; o >>= 1) s += __shfl_xor_sync(0xffffffffu, s, o);
        if (lane == 0) out[((size_t)n * MAXLEN + step) * VOCAB + v] = s + b_out[v];
    }
}

// ---------------------------------------------------------------------------
// kernel_launch: init (3 kernels) + 300 x (lstm1, lstm2, attn)
// ---------------------------------------------------------------------------
extern "C" void kernel_launch(void* const* d_in, const int* in_sizes, int n_in,
                              void* d_out, int out_size)
{
    const float* enc_key    = (const float*)d_in[0];
    const float* enc_values = (const float*)d_in[1];
    const int*   text       = (const int*)  d_in[2];
    const int*   lens       = (const int*)  d_in[3];
    const float* emb        = (const float*)d_in[5];
    const float* W_ih1      = (const float*)d_in[6];
    const float* W_hh1      = (const float*)d_in[7];
    const float* b_ih1      = (const float*)d_in[8];
    const float* b_hh1      = (const float*)d_in[9];
    const float* W_ih2      = (const float*)d_in[10];
    const float* W_hh2      = (const float*)d_in[11];
    const float* b_ih2      = (const float*)d_in[12];
    const float* b_hh2      = (const float*)d_in[13];
    const float* W_out      = (const float*)d_in[14];
    const float* b_out      = (const float*)d_in[15];
    float* out = (float*)d_out;

    init_misc<<<1024, 256>>>(W_ih1, W_hh1, W_ih2, W_hh2, b_ih2, b_hh2, lens);
    embB_kernel<<<dim3(VOCAB, 8), 256>>>(emb, W_ih1, b_ih1, b_hh1);
    sort_kernel<<<1, 256>>>();

    for (int t = 0; t < MAXLEN; t++) {
        int par = t & 1;
        lstm1_kernel<<<dim3(32, 8), 128>>>(text, t, par);
        lstm2_kernel<<<dim3(16, 8), 256>>>(par);
        attn_kernel<<<NB, 512>>>(enc_key, enc_values, W_out, b_out, out, t, par);
    }
}

// round 10
// speedup vs baseline: 1.6112x; 1.0022x over previous
#include <cuda_runtime.h>
#include <cuda_bf16.h>
#include <math.h>

// ---------------------------------------------------------------------------
// Problem constants
// ---------------------------------------------------------------------------
#define NB      256
#define HH      512
#define KSZ     256
#define VSZ     256
#define TT      512
#define TEXTLEN 301
#define MAXLEN  300
#define VOCAB   35

#define K1      768     // ctx(256) + h1(512)   (emb part folded into table)
#define K2      768     // h1(512) + h2(256)
#define R1      2048    // 4*H   rows, packed r = h*4 + gate
#define R2      1024    // 4*KS  rows, packed r = h*4 + gate

// ---------------------------------------------------------------------------
// Device scratch
// ---------------------------------------------------------------------------
__device__ float g_W1T[K1 * R1];          // [k][r] transposed, gate-interleaved
__device__ float g_W2T[K2 * R2];
__device__ float g_embB[VOCAB * R1];      // emb@W_ih1[:, :512]^T + b_ih1 + b_hh1
__device__ float g_b2p[R2];               // b_ih2 + b_hh2, packed order
__device__ float g_h1[2][NB * HH];
__device__ float g_c1[NB * HH];
__device__ float g_h2[2][NB * KSZ];
__device__ float g_c2[NB * KSZ];
__device__ float g_ctx[NB * VSZ];
__device__ int g_nv[NB];
__device__ int g_order[NB];

__device__ __forceinline__ float sigmoidf_(float x) { return 1.f / (1.f + expf(-x)); }

// ---------------------------------------------------------------------------
// Init 1: weight transposes (gate-interleaved), packed bias, states, nv.
// ---------------------------------------------------------------------------
__global__ void init_misc(const float* __restrict__ Wih1, const float* __restrict__ Whh1,
                          const float* __restrict__ Wih2, const float* __restrict__ Whh2,
                          const float* __restrict__ bih2, const float* __restrict__ bhh2,
                          const int* __restrict__ lens)
{
    int idx = blockIdx.x * blockDim.x + threadIdx.x;
    int stride = gridDim.x * blockDim.x;

    for (int i = idx; i < K1 * R1; i += stride) {
        int k = i >> 11, r = i & (R1 - 1);
        int h = r >> 2, g = r & 3, ro = g * 512 + h;
        g_W1T[i] = (k < 256) ? Wih1[ro * 768 + 512 + k]       // ctx columns
                             : Whh1[ro * 512 + (k - 256)];    // h1 columns
    }
    for (int i = idx; i < K2 * R2; i += stride) {
        int k = i >> 10, r = i & (R2 - 1);
        int h = r >> 2, g = r & 3, ro = g * 256 + h;
        g_W2T[i] = (k < 512) ? Wih2[ro * 512 + k]
                             : Whh2[ro * 256 + (k - 512)];
    }
    for (int r = idx; r < R2; r += stride) {
        int h = r >> 2, g = r & 3, ro = g * 256 + h;
        g_b2p[r] = bih2[ro] + bhh2[ro];
    }
    for (int i = idx; i < NB * HH; i += stride) {
        g_h1[0][i] = 0.f; g_h1[1][i] = 0.f; g_c1[i] = 0.f;
    }
    for (int i = idx; i < NB * KSZ; i += stride) {
        g_h2[0][i] = 0.f; g_h2[1][i] = 0.f; g_c2[i] = 0.f; g_ctx[i] = 0.f;
    }
    for (int n = idx; n < NB; n += stride) {
        int v = lens[n] >> 3;
        if (v < 1)  v = 1;
        if (v > TT) v = TT;
        g_nv[n] = v;
    }
}

// ---------------------------------------------------------------------------
// Init 2: per-vocab precomputed gate base: emb[v] @ W_ih1[:, :512]^T + biases.
// ---------------------------------------------------------------------------
__global__ void embB_kernel(const float* __restrict__ emb, const float* __restrict__ Wih1,
                            const float* __restrict__ bih1, const float* __restrict__ bhh1)
{
    __shared__ float se[512];
    int v = blockIdx.x;
    int tid = threadIdx.x;
    se[tid]       = emb[v * HH + tid];
    se[tid + 256] = emb[v * HH + tid + 256];
    __syncthreads();
    int r = blockIdx.y * 256 + tid;
    int h = r >> 2, g = r & 3, ro = g * 512 + h;
    float acc = bih1[ro] + bhh1[ro];
    const float* __restrict__ wr = Wih1 + (size_t)ro * 768;
#pragma unroll 8
    for (int k = 0; k < 512; k++) acc = fmaf(se[k], wr[k], acc);
    g_embB[v * R1 + r] = acc;
}

// ---------------------------------------------------------------------------
// Init 3: sort batch rows by nv desc (scheduling order for attn tail).
// ---------------------------------------------------------------------------
__global__ void sort_kernel()
{
    __shared__ int snv[NB];
    int tid = threadIdx.x;
    snv[tid] = g_nv[tid];
    __syncthreads();
    int my = snv[tid];
    int rank = 0;
    for (int m = 0; m < NB; m++)
        rank += (snv[m] > my) || (snv[m] == my && m < tid);
    g_order[rank] = tid;
}

// ---------------------------------------------------------------------------
// LSTM1: gates = [ctx | h1] @ W1T + embB[tok];  cell update.
// Tile 64 rows x 32 batch, 128 threads, thread tile 4r x 4n (16 acc).
// Double-buffered (reg prefetch), ONE sync per 32-k chunk.
// Grid (32, 8) = 256 blocks -> 2 independent blocks per SM.
// ---------------------------------------------------------------------------
#define L1_NC   (K1 / 32)     // 24 chunks
#define AS1_STR 36

__global__ __launch_bounds__(128) void lstm1_kernel(const int* __restrict__ text,
                                                    int step, int par)
{
    __shared__ float Ws[2][32][64];
    __shared__ float As[2][32][AS1_STR];

    const int tid = threadIdx.x;
    const int tx = tid & 15;          // r-group: rows rb + tx*4 .. +3
    const int ty = tid >> 4;          // n-group: cols nb + ty*4 .. +3 (0..7)
    const int rb = blockIdx.x * 64;
    const int nb = blockIdx.y * 32;

    const float* __restrict__ h1p = g_h1[par];
    float* __restrict__ h1n = g_h1[par ^ 1];

    // staging thread mapping
    const int wc4 = tid & 15;         // W float4 column
    const int wk0 = tid >> 4;         // W k rows wk0 + 8j, j=0..3
    const int an  = tid >> 2;         // A batch row nb+an (0..31)
    const int ak  = tid & 3;          // A k offsets ak + 4j, j=0..7

    float acc[4][4];
#pragma unroll
    for (int i = 0; i < 4; i++)
#pragma unroll
        for (int j = 0; j < 4; j++) acc[i][j] = 0.f;

    float4 wreg[4];
    float  areg[8];

    // ---- prologue: load + store chunk 0 ----
    {
#pragma unroll
        for (int j = 0; j < 4; j++)
            wreg[j] = *(const float4*)&g_W1T[(size_t)(wk0 + 8 * j) * R1 + rb + wc4 * 4];
        const float* abase = g_ctx + (size_t)(nb + an) * VSZ + ak;
#pragma unroll
        for (int j = 0; j < 8; j++) areg[j] = abase[4 * j];
#pragma unroll
        for (int j = 0; j < 4; j++)
            *(float4*)&Ws[0][wk0 + 8 * j][wc4 * 4] = wreg[j];
#pragma unroll
        for (int j = 0; j < 8; j++) As[0][ak + 4 * j][an] = areg[j];
    }
    __syncthreads();

#pragma unroll 1
    for (int c = 0; c < L1_NC; c++) {
        // prefetch chunk c+1 into registers
        if (c + 1 < L1_NC) {
            const int k0 = (c + 1) * 32;
#pragma unroll
            for (int j = 0; j < 4; j++)
                wreg[j] = *(const float4*)&g_W1T[(size_t)(k0 + wk0 + 8 * j) * R1 + rb + wc4 * 4];
            const float* abase = (k0 < 256)
                ? g_ctx + (size_t)(nb + an) * VSZ + (k0 + ak)
                : h1p   + (size_t)(nb + an) * HH  + (k0 - 256 + ak);
#pragma unroll
            for (int j = 0; j < 8; j++) areg[j] = abase[4 * j];
        }
        // compute current buffer
        const int buf = c & 1;
#pragma unroll
        for (int k = 0; k < 32; k++) {
            float4 w = *(float4*)&Ws[buf][k][tx * 4];
            float4 a = *(float4*)&As[buf][k][ty * 4];
            acc[0][0] = fmaf(w.x, a.x, acc[0][0]); acc[0][1] = fmaf(w.x, a.y, acc[0][1]);
            acc[0][2] = fmaf(w.x, a.z, acc[0][2]); acc[0][3] = fmaf(w.x, a.w, acc[0][3]);
            acc[1][0] = fmaf(w.y, a.x, acc[1][0]); acc[1][1] = fmaf(w.y, a.y, acc[1][1]);
            acc[1][2] = fmaf(w.y, a.z, acc[1][2]); acc[1][3] = fmaf(w.y, a.w, acc[1][3]);
            acc[2][0] = fmaf(w.z, a.x, acc[2][0]); acc[2][1] = fmaf(w.z, a.y, acc[2][1]);
            acc[2][2] = fmaf(w.z, a.z, acc[2][2]); acc[2][3] = fmaf(w.z, a.w, acc[2][3]);
            acc[3][0] = fmaf(w.w, a.x, acc[3][0]); acc[3][1] = fmaf(w.w, a.y, acc[3][1]);
            acc[3][2] = fmaf(w.w, a.z, acc[3][2]); acc[3][3] = fmaf(w.w, a.w, acc[3][3]);
        }
        // store prefetched chunk into alternate buffer
        if (c + 1 < L1_NC) {
            const int nbuf = buf ^ 1;
#pragma unroll
            for (int j = 0; j < 4; j++)
                *(float4*)&Ws[nbuf][wk0 + 8 * j][wc4 * 4] = wreg[j];
#pragma unroll
            for (int j = 0; j < 8; j++) As[nbuf][ak + 4 * j][an] = areg[j];
            __syncthreads();
        }
    }

    // ---- epilogue: add embB[tok], cell update ----
    const int h = (rb >> 2) + tx;          // hidden index (4 gates per h)
#pragma unroll
    for (int j = 0; j < 4; j++) {
        int n = nb + ty * 4 + j;
        int tok = __ldg(&text[n * TEXTLEN + step]);
        float4 eb = *(const float4*)&g_embB[tok * R1 + rb + tx * 4];
        float gi = acc[0][j] + eb.x;
        float gf = acc[1][j] + eb.y;
        float gg = acc[2][j] + eb.z;
        float go = acc[3][j] + eb.w;
        float c = sigmoidf_(gf) * g_c1[n * HH + h] + sigmoidf_(gi) * tanhf(gg);
        g_c1[n * HH + h] = c;
        h1n[n * HH + h] = sigmoidf_(go) * tanhf(c);
    }
}

// ---------------------------------------------------------------------------
// LSTM2: gates = [h1_new | h2] @ W2T + b2p;  cell update.   (R7 version)
// Tile 64 rows x 32 batch, 256 threads, thread tile 4r x 2n.
// Double-buffered, one sync per chunk. Grid (16, 8) = 128 blocks.
// ---------------------------------------------------------------------------
#define L2_NC   (K2 / 32)     // 24 chunks
#define AS2_STR 34

__global__ __launch_bounds__(256) void lstm2_kernel(int par)
{
    __shared__ float Ws[2][32][64];
    __shared__ float As[2][32][AS2_STR];

    const int tid = threadIdx.x;
    const int tx = tid & 15;          // r-group
    const int ty = tid >> 4;          // n-pair: cols nb + ty*2, +1
    const int rb = blockIdx.x * 64;
    const int nb = blockIdx.y * 32;

    const float* __restrict__ h1n = g_h1[par ^ 1];
    const float* __restrict__ h2p = g_h2[par];
    float* __restrict__ h2n = g_h2[par ^ 1];

    const int wk = tid >> 4;
    const int wc4 = tid & 15;
    const int an = tid >> 3;          // 0..31
    const int ak = tid & 7;           // k offsets ak + 8j, j=0..3

    float acc[4][2];
#pragma unroll
    for (int i = 0; i < 4; i++) { acc[i][0] = 0.f; acc[i][1] = 0.f; }

    float4 wreg0, wreg1;
    float areg[4];

    {
        const int k0 = 0;
        wreg0 = *(const float4*)&g_W2T[(size_t)(k0 + wk) * R2 + rb + wc4 * 4];
        wreg1 = *(const float4*)&g_W2T[(size_t)(k0 + wk + 16) * R2 + rb + wc4 * 4];
        const float* abase = h1n + (size_t)(nb + an) * HH + (k0 + ak);
#pragma unroll
        for (int j = 0; j < 4; j++) areg[j] = abase[8 * j];
        *(float4*)&Ws[0][wk][wc4 * 4]      = wreg0;
        *(float4*)&Ws[0][wk + 16][wc4 * 4] = wreg1;
#pragma unroll
        for (int j = 0; j < 4; j++) As[0][ak + 8 * j][an] = areg[j];
    }
    __syncthreads();

#pragma unroll 1
    for (int c = 0; c < L2_NC; c++) {
        if (c + 1 < L2_NC) {
            const int k0 = (c + 1) * 32;
            wreg0 = *(const float4*)&g_W2T[(size_t)(k0 + wk) * R2 + rb + wc4 * 4];
            wreg1 = *(const float4*)&g_W2T[(size_t)(k0 + wk + 16) * R2 + rb + wc4 * 4];
            const float* abase = (k0 < 512)
                ? h1n + (size_t)(nb + an) * HH  + (k0 + ak)
                : h2p + (size_t)(nb + an) * KSZ + (k0 - 512 + ak);
#pragma unroll
            for (int j = 0; j < 4; j++) areg[j] = abase[8 * j];
        }
        const int buf = c & 1;
#pragma unroll
        for (int k = 0; k < 32; k++) {
            float4 w = *(float4*)&Ws[buf][k][tx * 4];
            float2 a = *(float2*)&As[buf][k][ty * 2];
            acc[0][0] = fmaf(w.x, a.x, acc[0][0]); acc[0][1] = fmaf(w.x, a.y, acc[0][1]);
            acc[1][0] = fmaf(w.y, a.x, acc[1][0]); acc[1][1] = fmaf(w.y, a.y, acc[1][1]);
            acc[2][0] = fmaf(w.z, a.x, acc[2][0]); acc[2][1] = fmaf(w.z, a.y, acc[2][1]);
            acc[3][0] = fmaf(w.w, a.x, acc[3][0]); acc[3][1] = fmaf(w.w, a.y, acc[3][1]);
        }
        if (c + 1 < L2_NC) {
            const int nbuf = buf ^ 1;
            *(float4*)&Ws[nbuf][wk][wc4 * 4]      = wreg0;
            *(float4*)&Ws[nbuf][wk + 16][wc4 * 4] = wreg1;
#pragma unroll
            for (int j = 0; j < 4; j++) As[nbuf][ak + 8 * j][an] = areg[j];
            __syncthreads();
        }
    }

    const int h = (rb >> 2) + tx;
    const int r4 = rb + tx * 4;
    const float bi = g_b2p[r4 + 0];
    const float bf = g_b2p[r4 + 1];
    const float bg = g_b2p[r4 + 2];
    const float bo = g_b2p[r4 + 3];
#pragma unroll
    for (int j = 0; j < 2; j++) {
        int n = nb + ty * 2 + j;
        float gi = acc[0][j] + bi;
        float gf = acc[1][j] + bf;
        float gg = acc[2][j] + bg;
        float go = acc[3][j] + bo;
        float c = sigmoidf_(gf) * g_c2[n * KSZ + h] + sigmoidf_(gi) * tanhf(gg);
        g_c2[n * KSZ + h] = c;
        h2n[n * KSZ + h] = sigmoidf_(go) * tanhf(c);
    }
}

// ---------------------------------------------------------------------------
// Attention + output projection, fp32 K/V, high-MLP.  (unchanged, R5-proven)
// One block per batch row (length-sorted order), 512 threads / 16 warps.
// ---------------------------------------------------------------------------
__global__ __launch_bounds__(512) void attn_kernel(const float* __restrict__ enc_key,
                                                   const float* __restrict__ enc_values,
                                                   const float* __restrict__ W_out,
                                                   const float* __restrict__ b_out,
                                                   float* __restrict__ out,
                                                   int step, int par)
{
    __shared__ float sh_q[KSZ];
    __shared__ float sh_c[VSZ];
    __shared__ float sh_e[TT];
    __shared__ float sh_red[16];
    __shared__ float sh_inv;
    __shared__ float sh_acc[16][VSZ];

    const int tid = threadIdx.x;
    const int lane = tid & 31;
    const int warp = tid >> 5;
    const int n = g_order[blockIdx.x];
    const int nv = g_nv[n];

    if (tid < KSZ) sh_q[tid] = g_h2[par ^ 1][n * KSZ + tid];
    __syncthreads();

    float qr[8];
#pragma unroll
    for (int i = 0; i < 8; i++) qr[i] = sh_q[lane * 8 + i];

    // ---- energies ----
    const float* __restrict__ Kb = enc_key + (size_t)n * TT * KSZ;
    float lmax = -1e30f;
    for (int c = 0; c < nv; c += 64) {
        float4 ka[4], kb[4];
        bool act[4];
#pragma unroll
        for (int u = 0; u < 4; u++) {
            int t = c + warp + 16 * u;
            act[u] = (t < nv);
            if (act[u]) {
                const float* kr = Kb + (size_t)t * KSZ + lane * 8;
                ka[u] = *(const float4*)kr;
                kb[u] = *(const float4*)(kr + 4);
            }
        }
#pragma unroll
        for (int u = 0; u < 4; u++) {
            if (act[u]) {
                float s = qr[0] * ka[u].x + qr[1] * ka[u].y + qr[2] * ka[u].z + qr[3] * ka[u].w
                        + qr[4] * kb[u].x + qr[5] * kb[u].y + qr[6] * kb[u].z + qr[7] * kb[u].w;
#pragma unroll
                for (int o = 16; o; o >>= 1) s += __shfl_xor_sync(0xffffffffu, s, o);
                if (lane == 0) sh_e[c + warp + 16 * u] = s;
                lmax = fmaxf(lmax, s);
            }
        }
    }
    if (lane == 0) sh_red[warp] = lmax;
    __syncthreads();

    float emax = sh_red[0];
#pragma unroll
    for (int w = 1; w < 16; w++) emax = fmaxf(emax, sh_red[w]);

    float lsum = 0.f;
    for (int t = tid; t < nv; t += 512) {
        float e = expf(sh_e[t] - emax);
        sh_e[t] = e;
        lsum += e;
    }
#pragma unroll
    for (int o = 16; o; o >>= 1) lsum += __shfl_xor_sync(0xffffffffu, lsum, o);
    __syncthreads();
    if (lane == 0) sh_red[warp] = lsum;
    __syncthreads();
    if (tid == 0) {
        float tot = 0.f;
#pragma unroll
        for (int w = 0; w < 16; w++) tot += sh_red[w];
        sh_inv = 1.f / tot;
    }
    __syncthreads();
    const float inv = sh_inv;

    // ---- context ----
    const float* __restrict__ Vb = enc_values + (size_t)n * TT * VSZ;
    float acc[8];
#pragma unroll
    for (int i = 0; i < 8; i++) acc[i] = 0.f;
    for (int c = 0; c < nv; c += 64) {
        float4 va[4], vb[4];
        float ew[4];
        bool act[4];
#pragma unroll
        for (int u = 0; u < 4; u++) {
            int t = c + warp + 16 * u;
            act[u] = (t < nv);
            if (act[u]) {
                const float* vr = Vb + (size_t)t * VSZ + lane * 8;
                va[u] = *(const float4*)vr;
                vb[u] = *(const float4*)(vr + 4);
                ew[u] = sh_e[t];
            }
        }
#pragma unroll
        for (int u = 0; u < 4; u++) {
            if (act[u]) {
                float e = ew[u];
                acc[0] = fmaf(e, va[u].x, acc[0]); acc[1] = fmaf(e, va[u].y, acc[1]);
                acc[2] = fmaf(e, va[u].z, acc[2]); acc[3] = fmaf(e, va[u].w, acc[3]);
                acc[4] = fmaf(e, vb[u].x, acc[4]); acc[5] = fmaf(e, vb[u].y, acc[5]);
                acc[6] = fmaf(e, vb[u].z, acc[6]); acc[7] = fmaf(e, vb[u].w, acc[7]);
            }
        }
    }
#pragma unroll
    for (int i = 0; i < 8; i++) sh_acc[warp][lane * 8 + i] = acc[i];
    __syncthreads();

    if (tid < VSZ) {
        float ctx = 0.f;
#pragma unroll
        for (int w = 0; w < 16; w++) ctx += sh_acc[w][tid];
        ctx *= inv;
        sh_c[tid] = ctx;
        g_ctx[n * VSZ + tid] = ctx;
    }
    __syncthreads();

    // ---- output projection ----
    for (int v = warp; v < VOCAB; v += 16) {
        float s = 0.f;
        const float* __restrict__ wr = W_out + v * (KSZ + VSZ);
#pragma unroll
        for (int i = lane; i < KSZ + VSZ; i += 32) {
            float f = (i < KSZ) ? sh_q[i] : sh_c[i - KSZ];
            s = fmaf(f, wr[i], s);
        }
#pragma unroll
        for (int o = 16; o; o >>= 1) s += __shfl_xor_sync(0xffffffffu, s, o);
        if (lane == 0) out[((size_t)n * MAXLEN + step) * VOCAB + v] = s + b_out[v];
    }
}

// ---------------------------------------------------------------------------
// kernel_launch: init (3 kernels) + 300 x (lstm1, lstm2, attn)
// ---------------------------------------------------------------------------
extern "C" void kernel_launch(void* const* d_in, const int* in_sizes, int n_in,
                              void* d_out, int out_size)
{
    const float* enc_key    = (const float*)d_in[0];
    const float* enc_values = (const float*)d_in[1];
    const int*   text       = (const int*)  d_in[2];
    const int*   lens       = (const int*)  d_in[3];
    const float* emb        = (const float*)d_in[5];
    const float* W_ih1      = (const float*)d_in[6];
    const float* W_hh1      = (const float*)d_in[7];
    const float* b_ih1      = (const float*)d_in[8];
    const float* b_hh1      = (const float*)d_in[9];
    const float* W_ih2      = (const float*)d_in[10];
    const float* W_hh2      = (const float*)d_in[11];
    const float* b_ih2      = (const float*)d_in[12];
    const float* b_hh2      = (const float*)d_in[13];
    const float* W_out      = (const float*)d_in[14];
    const float* b_out      = (const float*)d_in[15];
    float* out = (float*)d_out;

    init_misc<<<1024, 256>>>(W_ih1, W_hh1, W_ih2, W_hh2, b_ih2, b_hh2, lens);
    embB_kernel<<<dim3(VOCAB, 8), 256>>>(emb, W_ih1, b_ih1, b_hh1);
    sort_kernel<<<1, 256>>>();

    for (int t = 0; t < MAXLEN; t++) {
        int par = t & 1;
        lstm1_kernel<<<dim3(32, 8), 128>>>(text, t, par);
        lstm2_kernel<<<dim3(16, 8), 256>>>(par);
        attn_kernel<<<NB, 512>>>(enc_key, enc_values, W_out, b_out, out, t, par);
    }
}